// round 1
// baseline (speedup 1.0000x reference)
#include <cuda_runtime.h>
#include <cuda_bf16.h>

#define B_  8
#define C_  1024
#define T_  1024
#define H_  16
#define KC_ 64
#define RS_ 68   // smem row stride (floats) for flash tiles

// Scratch (static device globals — no allocations)
__device__ float g_q[(size_t)B_*H_*T_*KC_];
__device__ float g_k[(size_t)B_*H_*T_*KC_];
__device__ float g_v[(size_t)B_*H_*T_*KC_];
__device__ float g_attn[(size_t)B_*C_*T_];

// ---------------------------------------------------------------------------
// Pointwise-conv projection GEMM:  out[b,o,t] = sum_c W[o,c] * X[b,c,t] + bias[o]
// mode 0: write g_q as [b,h,t,ch] scaled by `scale`
// mode 1: write g_k as [b,h,t,ch]
// mode 2: write g_v as [b,h,t,ch]
// mode 3: X := g_attn, write dout as [b,o,t]
// ---------------------------------------------------------------------------
__global__ __launch_bounds__(256) void proj_kernel(
    const float* __restrict__ W, const float* __restrict__ Xin,
    const float* __restrict__ bias, float* __restrict__ dout,
    float scale, int mode)
{
    const float* X = (mode == 3) ? (const float*)g_attn : Xin;
    const int b  = blockIdx.z;
    const int o0 = blockIdx.y * 64;
    const int t0 = blockIdx.x * 64;
    const int tid = threadIdx.x;
    const int tx = tid & 15, ty = tid >> 4;

    __shared__ float Ws[16][64];  // [k][o]
    __shared__ float Xs[16][64];  // [k][t]

    float acc[4][4];
    #pragma unroll
    for (int i = 0; i < 4; i++)
        #pragma unroll
        for (int j = 0; j < 4; j++) acc[i][j] = 0.f;

    const float* Xb = X + (size_t)b * C_ * T_;

    const int wrow = tid >> 2;         // 0..63
    const int wc4  = (tid & 3) * 4;    // 0,4,8,12
    const int xr   = tid >> 4;         // 0..15
    const int xc4  = (tid & 15) * 4;   // 0..60

    for (int k0 = 0; k0 < C_; k0 += 16) {
        float4 w  = *(const float4*)(W  + (size_t)(o0 + wrow) * C_ + k0 + wc4);
        float4 xv = *(const float4*)(Xb + (size_t)(k0 + xr)  * T_ + t0 + xc4);
        Ws[wc4+0][wrow] = w.x; Ws[wc4+1][wrow] = w.y;
        Ws[wc4+2][wrow] = w.z; Ws[wc4+3][wrow] = w.w;
        *(float4*)&Xs[xr][xc4] = xv;
        __syncthreads();
        #pragma unroll
        for (int kk = 0; kk < 16; kk++) {
            float4 a  = *(const float4*)&Ws[kk][ty*4];
            float4 bb = *(const float4*)&Xs[kk][tx*4];
            float av[4] = {a.x, a.y, a.z, a.w};
            float bv[4] = {bb.x, bb.y, bb.z, bb.w};
            #pragma unroll
            for (int i = 0; i < 4; i++)
                #pragma unroll
                for (int j = 0; j < 4; j++)
                    acc[i][j] = fmaf(av[i], bv[j], acc[i][j]);
        }
        __syncthreads();
    }

    if (mode == 3) {
        #pragma unroll
        for (int i = 0; i < 4; i++) {
            int o = o0 + ty*4 + i;
            float bi = bias[o];
            float4 v = make_float4(acc[i][0]+bi, acc[i][1]+bi, acc[i][2]+bi, acc[i][3]+bi);
            *(float4*)(dout + ((size_t)b * C_ + o) * T_ + t0 + tx*4) = v;
        }
    } else {
        float* outp = (mode == 0) ? g_q : (mode == 1) ? g_k : g_v;
        #pragma unroll
        for (int i = 0; i < 4; i++) {
            int o = o0 + ty*4 + i;
            float bi = bias[o];
            int h = o >> 6, ch = o & 63;
            float* base = outp + ((size_t)b * H_ + h) * T_ * KC_;
            #pragma unroll
            for (int j = 0; j < 4; j++) {
                int t = t0 + tx*4 + j;
                base[(size_t)t * KC_ + ch] = (acc[i][j] + bi) * scale;
            }
        }
    }
}

// ---------------------------------------------------------------------------
// Flash attention per (b, h) with relative-position key bias.
// bias[t,s] = Rb[t][clip(s-t,-4,4)+4],  Rb[t][j] = (scaled q_t) . emb_rel_k[j]
// grid: (T/64, H, B), 256 threads, online softmax, fp32.
// Writes attention output to g_attn as [b, h*64+ch, t].
// ---------------------------------------------------------------------------
#define FLASH_SMEM_BYTES ((4*64*RS_ + 9*64 + 64*12) * 4)

__global__ __launch_bounds__(256) void flash_kernel(const float* __restrict__ emb)
{
    extern __shared__ float sm[];
    float* Qt = sm;               // [ch][r]  (64 x RS_)
    float* Kt = Qt + 64*RS_;      // [ch][s]
    float* Vs = Kt + 64*RS_;      // [s][ch]
    float* Pt = Vs + 64*RS_;      // [s][r]
    float* Eb = Pt + 64*RS_;      // [9][64]
    float* Rb = Eb + 9*64;        // [r][12]

    const int b = blockIdx.z, h = blockIdx.y;
    const int q0 = blockIdx.x * 64;
    const int tid = threadIdx.x;
    const int tx = tid & 15, ty = tid >> 4;

    const size_t bh = ((size_t)b * H_ + h) * T_ * KC_;
    const float* Qg = g_q + bh;
    const float* Kg = g_k + bh;
    const float* Vg = g_v + bh;

    // Load Q transposed into Qt[ch][r]
    {
        int r0 = tid >> 4;
        int c  = (tid & 15) * 4;
        #pragma unroll
        for (int it = 0; it < 4; it++) {
            int r = r0 + it*16;
            float4 v = *(const float4*)(Qg + (size_t)(q0 + r) * KC_ + c);
            Qt[(c+0)*RS_ + r] = v.x;
            Qt[(c+1)*RS_ + r] = v.y;
            Qt[(c+2)*RS_ + r] = v.z;
            Qt[(c+3)*RS_ + r] = v.w;
        }
    }
    if (tid < 144) ((float4*)Eb)[tid] = ((const float4*)emb)[tid];  // 9*64 floats
    __syncthreads();

    // Rb[r][j] = sum_ch Qt[ch][r] * Eb[j][ch]   (q already scaled)
    {
        int r = tid & 63;
        for (int j = tid >> 6; j < 9; j += 4) {
            float s = 0.f;
            #pragma unroll
            for (int ch = 0; ch < 64; ch++)
                s = fmaf(Qt[ch*RS_ + r], Eb[j*64 + ch], s);
            Rb[r*12 + j] = s;
        }
    }
    // (first loop-top __syncthreads covers Rb visibility)

    float m[4], l[4], o[4][4];
    #pragma unroll
    for (int i = 0; i < 4; i++) {
        m[i] = -1e30f; l[i] = 0.f;
        #pragma unroll
        for (int j = 0; j < 4; j++) o[i][j] = 0.f;
    }

    for (int k0 = 0; k0 < T_; k0 += 64) {
        __syncthreads();  // protect Kt/Vs/Pt from previous iteration readers
        {
            int r0 = tid >> 4;
            int c  = (tid & 15) * 4;
            #pragma unroll
            for (int it = 0; it < 4; it++) {
                int r = r0 + it*16;
                float4 kv = *(const float4*)(Kg + (size_t)(k0 + r) * KC_ + c);
                Kt[(c+0)*RS_ + r] = kv.x;
                Kt[(c+1)*RS_ + r] = kv.y;
                Kt[(c+2)*RS_ + r] = kv.z;
                Kt[(c+3)*RS_ + r] = kv.w;
                float4 vv = *(const float4*)(Vg + (size_t)(k0 + r) * KC_ + c);
                *(float4*)&Vs[r*RS_ + c] = vv;
            }
        }
        __syncthreads();

        // S = Q K^T  (thread tile 4x4, inner over ch)
        float s_acc[4][4];
        #pragma unroll
        for (int i = 0; i < 4; i++)
            #pragma unroll
            for (int j = 0; j < 4; j++) s_acc[i][j] = 0.f;

        #pragma unroll 8
        for (int ch = 0; ch < 64; ch++) {
            float4 a  = *(const float4*)&Qt[ch*RS_ + ty*4];
            float4 bb = *(const float4*)&Kt[ch*RS_ + tx*4];
            float av[4] = {a.x, a.y, a.z, a.w};
            float bv[4] = {bb.x, bb.y, bb.z, bb.w};
            #pragma unroll
            for (int i = 0; i < 4; i++)
                #pragma unroll
                for (int j = 0; j < 4; j++)
                    s_acc[i][j] = fmaf(av[i], bv[j], s_acc[i][j]);
        }

        // relative-position bias
        #pragma unroll
        for (int i = 0; i < 4; i++) {
            int tg = q0 + ty*4 + i;
            #pragma unroll
            for (int j = 0; j < 4; j++) {
                int d = (k0 + tx*4 + j) - tg;
                d = min(max(d, -4), 4) + 4;
                s_acc[i][j] += Rb[(ty*4 + i)*12 + d];
            }
        }

        // online softmax (row groups = 16 lanes sharing ty)
        float p[4][4];
        #pragma unroll
        for (int i = 0; i < 4; i++) {
            float mx = fmaxf(fmaxf(s_acc[i][0], s_acc[i][1]),
                             fmaxf(s_acc[i][2], s_acc[i][3]));
            #pragma unroll
            for (int off = 8; off > 0; off >>= 1)
                mx = fmaxf(mx, __shfl_xor_sync(0xffffffffu, mx, off));
            float mnew = fmaxf(m[i], mx);
            float rsum = 0.f;
            #pragma unroll
            for (int j = 0; j < 4; j++) {
                float e = __expf(s_acc[i][j] - mnew);
                p[i][j] = e; rsum += e;
            }
            #pragma unroll
            for (int off = 8; off > 0; off >>= 1)
                rsum += __shfl_xor_sync(0xffffffffu, rsum, off);
            float f = __expf(m[i] - mnew);
            l[i] = l[i]*f + rsum;
            #pragma unroll
            for (int j = 0; j < 4; j++) o[i][j] *= f;
            m[i] = mnew;
        }

        // P transposed to shared for PV
        #pragma unroll
        for (int i = 0; i < 4; i++)
            #pragma unroll
            for (int j = 0; j < 4; j++)
                Pt[(tx*4 + j)*RS_ + ty*4 + i] = p[i][j];
        __syncthreads();

        // O += P V
        #pragma unroll 8
        for (int s = 0; s < 64; s++) {
            float4 a  = *(const float4*)&Pt[s*RS_ + ty*4];
            float4 bb = *(const float4*)&Vs[s*RS_ + tx*4];
            float av[4] = {a.x, a.y, a.z, a.w};
            float bv[4] = {bb.x, bb.y, bb.z, bb.w};
            #pragma unroll
            for (int i = 0; i < 4; i++)
                #pragma unroll
                for (int j = 0; j < 4; j++)
                    o[i][j] = fmaf(av[i], bv[j], o[i][j]);
        }
    }

    float inv[4];
    #pragma unroll
    for (int i = 0; i < 4; i++) inv[i] = 1.f / l[i];
    #pragma unroll
    for (int j = 0; j < 4; j++) {
        int chan = h*64 + tx*4 + j;
        float4 w = make_float4(o[0][j]*inv[0], o[1][j]*inv[1],
                               o[2][j]*inv[2], o[3][j]*inv[3]);
        *(float4*)(g_attn + ((size_t)b * C_ + chan) * T_ + q0 + ty*4) = w;
    }
}

// ---------------------------------------------------------------------------
extern "C" void kernel_launch(void* const* d_in, const int* in_sizes, int n_in,
                              void* d_out, int out_size)
{
    const float* x   = (const float*)d_in[0];
    const float* c   = (const float*)d_in[1];
    const float* wq  = (const float*)d_in[2];
    const float* bq  = (const float*)d_in[3];
    const float* wk  = (const float*)d_in[4];
    const float* bk  = (const float*)d_in[5];
    const float* wv  = (const float*)d_in[6];
    const float* bv  = (const float*)d_in[7];
    const float* wo  = (const float*)d_in[8];
    const float* bo  = (const float*)d_in[9];
    const float* erk = (const float*)d_in[10];
    // d_in[11] = emb_rel_v: unused by the reference output

    dim3 grid(T_/64, C_/64, B_);
    dim3 blk(256);
    const float scale = 0.125f;  // 1/sqrt(64), baked into q

    proj_kernel<<<grid, blk>>>(wq, x, bq, nullptr, scale, 0);
    proj_kernel<<<grid, blk>>>(wk, c, bk, nullptr, 1.0f, 1);
    proj_kernel<<<grid, blk>>>(wv, c, bv, nullptr, 1.0f, 2);

    cudaFuncSetAttribute(flash_kernel,
                         cudaFuncAttributeMaxDynamicSharedMemorySize,
                         FLASH_SMEM_BYTES);
    dim3 fgrid(T_/64, H_, B_);
    flash_kernel<<<fgrid, blk, FLASH_SMEM_BYTES>>>(erk);

    proj_kernel<<<grid, blk>>>(wo, nullptr, bo, (float*)d_out, 1.0f, 3);
}

// round 2
// speedup vs baseline: 2.0626x; 2.0626x over previous
#include <cuda_runtime.h>
#include <cuda_bf16.h>
#include <cstdint>

#define B_  8
#define C_  1024
#define T_  1024
#define H_  16
#define KC_ 64

// Scratch (static device globals — no allocations)
__device__ float g_q[(size_t)B_*H_*T_*KC_];
__device__ float g_k[(size_t)B_*H_*T_*KC_];
__device__ float g_v[(size_t)B_*H_*T_*KC_];
__device__ float g_attn[(size_t)B_*C_*T_];

__device__ __forceinline__ float to_tf32(float x) {
    float r; asm("cvt.rna.tf32.f32 %0, %1;" : "=f"(r) : "f"(x)); return r;
}
__device__ __forceinline__ uint32_t fu(float x) { return __float_as_uint(x); }

__device__ __forceinline__ void mma_tf32(float* c, const uint32_t* a, const uint32_t* b) {
    asm volatile(
        "mma.sync.aligned.m16n8k8.row.col.f32.tf32.tf32.f32 "
        "{%0,%1,%2,%3}, {%4,%5,%6,%7}, {%8,%9}, {%0,%1,%2,%3};"
        : "+f"(c[0]), "+f"(c[1]), "+f"(c[2]), "+f"(c[3])
        : "r"(a[0]), "r"(a[1]), "r"(a[2]), "r"(a[3]), "r"(b[0]), "r"(b[1]));
}

// ---------------------------------------------------------------------------
// Projection GEMM via mma.tf32:  out[b,o,t] = sum_c W[o,c] * X[b,c,t] + bias[o]
// Block tile 128x128, K-stage 32. 8 warps (4m x 2n), warp tile 32x64.
// mode 0/1/2: write g_q/g_k/g_v as [b,h,t,ch] (*scale); mode 3: X=g_attn -> dout
// ---------------------------------------------------------------------------
__global__ __launch_bounds__(256) void gemm_mma(
    const float* __restrict__ W, const float* __restrict__ Xin,
    const float* __restrict__ bias, float* __restrict__ dout,
    float scale, int mode)
{
    const float* X = (mode == 3) ? (const float*)g_attn : Xin;
    const int b  = blockIdx.z;
    const int o0 = blockIdx.y * 128;
    const int t0 = blockIdx.x * 128;
    const int tid = threadIdx.x, lane = tid & 31, w = tid >> 5;
    const int wm = (w >> 1) * 32, wn = (w & 1) * 64;
    const int gid = lane >> 2, tig = lane & 3;

    __shared__ float As[32][132];   // [k][m]  (W tile, transposed)
    __shared__ float Bs[32][132];   // [k][n]  (X tile)

    float acc[2][8][4];
    #pragma unroll
    for (int mt = 0; mt < 2; mt++)
        #pragma unroll
        for (int nt = 0; nt < 8; nt++)
            #pragma unroll
            for (int r = 0; r < 4; r++) acc[mt][nt][r] = 0.f;

    const float* Xb = X + (size_t)b * C_ * T_;
    const int am = tid >> 1, ak = (tid & 1) * 16;
    const int bk = tid >> 3, bn = (tid & 7) * 16;
    const float* Wp = W  + (size_t)(o0 + am) * C_ + ak;
    const float* Xp = Xb + (size_t)bk * T_ + t0 + bn;

    for (int k0 = 0; k0 < C_; k0 += 32) {
        #pragma unroll
        for (int i = 0; i < 4; i++) {
            float4 wv = *(const float4*)(Wp + k0 + 4*i);
            As[ak+4*i+0][am] = to_tf32(wv.x);
            As[ak+4*i+1][am] = to_tf32(wv.y);
            As[ak+4*i+2][am] = to_tf32(wv.z);
            As[ak+4*i+3][am] = to_tf32(wv.w);
            float4 xv = *(const float4*)(Xp + (size_t)k0 * T_ + 4*i);
            xv.x = to_tf32(xv.x); xv.y = to_tf32(xv.y);
            xv.z = to_tf32(xv.z); xv.w = to_tf32(xv.w);
            *(float4*)&Bs[bk][bn + 4*i] = xv;
        }
        __syncthreads();
        #pragma unroll
        for (int kk = 0; kk < 32; kk += 8) {
            uint32_t a[2][4], bf[8][2];
            #pragma unroll
            for (int mt = 0; mt < 2; mt++) {
                int m = wm + 16*mt + gid;
                a[mt][0] = fu(As[kk+tig  ][m  ]);
                a[mt][1] = fu(As[kk+tig  ][m+8]);
                a[mt][2] = fu(As[kk+4+tig][m  ]);
                a[mt][3] = fu(As[kk+4+tig][m+8]);
            }
            #pragma unroll
            for (int nt = 0; nt < 8; nt++) {
                int n = wn + 8*nt + gid;
                bf[nt][0] = fu(Bs[kk+tig  ][n]);
                bf[nt][1] = fu(Bs[kk+4+tig][n]);
            }
            #pragma unroll
            for (int mt = 0; mt < 2; mt++)
                #pragma unroll
                for (int nt = 0; nt < 8; nt++)
                    mma_tf32(acc[mt][nt], a[mt], bf[nt]);
        }
        __syncthreads();
    }

    // Epilogue. C frag: c0=(r, 2*tig), c1=(r, 2*tig+1), c2=(r+8, ..), c3.
    if (mode == 3) {
        #pragma unroll
        for (int mt = 0; mt < 2; mt++) {
            int oa = o0 + wm + 16*mt + gid;
            int ob = oa + 8;
            float ba = bias[oa], bb = bias[ob];
            #pragma unroll
            for (int nt = 0; nt < 8; nt++) {
                int t = t0 + wn + 8*nt + 2*tig;
                float2 v01 = make_float2(acc[mt][nt][0] + ba, acc[mt][nt][1] + ba);
                float2 v23 = make_float2(acc[mt][nt][2] + bb, acc[mt][nt][3] + bb);
                *(float2*)(dout + ((size_t)b * C_ + oa) * T_ + t) = v01;
                *(float2*)(dout + ((size_t)b * C_ + ob) * T_ + t) = v23;
            }
        }
    } else {
        float* outp = (mode == 0) ? g_q : (mode == 1) ? g_k : g_v;
        #pragma unroll
        for (int mt = 0; mt < 2; mt++) {
            int oa = o0 + wm + 16*mt + gid;
            int ob = oa + 8;
            float ba = bias[oa], bb = bias[ob];
            int ha = oa >> 6, ca = oa & 63;
            int hb = ob >> 6, cb = ob & 63;
            float* pa = outp + ((size_t)b * H_ + ha) * T_ * KC_;
            float* pb = outp + ((size_t)b * H_ + hb) * T_ * KC_;
            #pragma unroll
            for (int nt = 0; nt < 8; nt++) {
                int t = t0 + wn + 8*nt + 2*tig;
                pa[(size_t)t     * KC_ + ca] = (acc[mt][nt][0] + ba) * scale;
                pa[(size_t)(t+1) * KC_ + ca] = (acc[mt][nt][1] + ba) * scale;
                pb[(size_t)t     * KC_ + cb] = (acc[mt][nt][2] + bb) * scale;
                pb[(size_t)(t+1) * KC_ + cb] = (acc[mt][nt][3] + bb) * scale;
            }
        }
    }
}

// ---------------------------------------------------------------------------
// Flash attention, mma.tf32. Q tile = 128 rows, 8 warps (one m16 slice each).
// bias[t,s] = Rb[t][clip(s-t,-4,4)+4],  Rb[t][j] = q_t . emb_rel_k[j]
// ---------------------------------------------------------------------------
#define FL_SMEM_FLOATS (128*68 + 64*68 + 64*68 + 128*68 + 576 + 1536)
#define FL_SMEM_BYTES  (FL_SMEM_FLOATS * 4)

__global__ __launch_bounds__(256) void flash_mma(const float* __restrict__ emb)
{
    extern __shared__ float sm[];
    float* Qs = sm;               // [128][68]  (tf32)
    float* Ks = Qs + 128*68;      // [64][68]
    float* Vs = Ks + 64*68;       // [64][68]
    float* Ps = Vs + 64*68;       // [128][68]  (tf32 probabilities)
    float* Eb = Ps + 128*68;      // [9][64]
    float* Rb = Eb + 576;         // [128][12]

    const int b = blockIdx.z, h = blockIdx.y, q0 = blockIdx.x * 128;
    const int tid = threadIdx.x, lane = tid & 31, w = tid >> 5;
    const int gid = lane >> 2, tig = lane & 3;
    const int wr = 16 * w;

    const size_t bh = ((size_t)b * H_ + h) * T_ * KC_;
    const float* Qg = g_q + bh;
    const float* Kg = g_k + bh;
    const float* Vg = g_v + bh;

    // Load Q tile (tf32-rounded)
    {
        int r = tid >> 1, c0 = (tid & 1) * 32;
        #pragma unroll
        for (int i = 0; i < 8; i++) {
            float4 v = *(const float4*)(Qg + (size_t)(q0 + r) * KC_ + c0 + 4*i);
            v.x = to_tf32(v.x); v.y = to_tf32(v.y);
            v.z = to_tf32(v.z); v.w = to_tf32(v.w);
            *(float4*)&Qs[r*68 + c0 + 4*i] = v;
        }
    }
    if (tid < 144) ((float4*)Eb)[tid] = ((const float4*)emb)[tid];  // 9*64 floats
    __syncthreads();

    // Rb[r][j] = sum_ch Qs[r][ch] * Eb[j][ch]   (q already scaled)
    {
        int r = tid & 127;
        for (int j = tid >> 7; j < 9; j += 2) {
            float s = 0.f;
            #pragma unroll
            for (int ch = 0; ch < 64; ch++)
                s = fmaf(Qs[r*68 + ch], Eb[j*64 + ch], s);
            Rb[r*12 + j] = s;
        }
    }
    __syncthreads();

    float m1 = -1e30f, m2 = -1e30f, l1 = 0.f, l2 = 0.f;
    float o[8][4];
    #pragma unroll
    for (int nt = 0; nt < 8; nt++)
        #pragma unroll
        for (int r = 0; r < 4; r++) o[nt][r] = 0.f;

    for (int k0 = 0; k0 < T_; k0 += 64) {
        __syncthreads();  // previous iteration's readers of Ks/Vs done
        {
            int r = tid >> 2, c0 = (tid & 3) * 16;
            #pragma unroll
            for (int i = 0; i < 4; i++) {
                float4 kv = *(const float4*)(Kg + (size_t)(k0 + r) * KC_ + c0 + 4*i);
                kv.x = to_tf32(kv.x); kv.y = to_tf32(kv.y);
                kv.z = to_tf32(kv.z); kv.w = to_tf32(kv.w);
                *(float4*)&Ks[r*68 + c0 + 4*i] = kv;
                float4 vv = *(const float4*)(Vg + (size_t)(k0 + r) * KC_ + c0 + 4*i);
                vv.x = to_tf32(vv.x); vv.y = to_tf32(vv.y);
                vv.z = to_tf32(vv.z); vv.w = to_tf32(vv.w);
                *(float4*)&Vs[r*68 + c0 + 4*i] = vv;
            }
        }
        __syncthreads();

        // S = Q K^T : m16 (q rows wr..wr+15) x n64 (s) x k64 (ch)
        float sc[8][4];
        #pragma unroll
        for (int nt = 0; nt < 8; nt++)
            #pragma unroll
            for (int r = 0; r < 4; r++) sc[nt][r] = 0.f;

        #pragma unroll
        for (int kk = 0; kk < 64; kk += 8) {
            uint32_t a[4];
            a[0] = fu(Qs[(wr+gid  )*68 + kk+tig  ]);
            a[1] = fu(Qs[(wr+gid+8)*68 + kk+tig  ]);
            a[2] = fu(Qs[(wr+gid  )*68 + kk+4+tig]);
            a[3] = fu(Qs[(wr+gid+8)*68 + kk+4+tig]);
            #pragma unroll
            for (int nt = 0; nt < 8; nt++) {
                uint32_t bf[2];
                bf[0] = fu(Ks[(8*nt+gid)*68 + kk+tig  ]);
                bf[1] = fu(Ks[(8*nt+gid)*68 + kk+4+tig]);
                mma_tf32(sc[nt], a, bf);
            }
        }

        // relative-position bias
        const int t1 = q0 + wr + gid, t2 = t1 + 8;
        #pragma unroll
        for (int nt = 0; nt < 8; nt++) {
            int s0 = k0 + 8*nt + 2*tig;
            int d0 = min(max(s0   - t1, -4), 4) + 4;
            int d1 = min(max(s0+1 - t1, -4), 4) + 4;
            int d2 = min(max(s0   - t2, -4), 4) + 4;
            int d3 = min(max(s0+1 - t2, -4), 4) + 4;
            sc[nt][0] += Rb[(wr+gid  )*12 + d0];
            sc[nt][1] += Rb[(wr+gid  )*12 + d1];
            sc[nt][2] += Rb[(wr+gid+8)*12 + d2];
            sc[nt][3] += Rb[(wr+gid+8)*12 + d3];
        }

        // online softmax for the two rows this thread covers
        float mx1 = -1e30f, mx2 = -1e30f;
        #pragma unroll
        for (int nt = 0; nt < 8; nt++) {
            mx1 = fmaxf(mx1, fmaxf(sc[nt][0], sc[nt][1]));
            mx2 = fmaxf(mx2, fmaxf(sc[nt][2], sc[nt][3]));
        }
        mx1 = fmaxf(mx1, __shfl_xor_sync(0xffffffffu, mx1, 1));
        mx1 = fmaxf(mx1, __shfl_xor_sync(0xffffffffu, mx1, 2));
        mx2 = fmaxf(mx2, __shfl_xor_sync(0xffffffffu, mx2, 1));
        mx2 = fmaxf(mx2, __shfl_xor_sync(0xffffffffu, mx2, 2));
        float mn1 = fmaxf(m1, mx1), mn2 = fmaxf(m2, mx2);

        float rs1 = 0.f, rs2 = 0.f;
        #pragma unroll
        for (int nt = 0; nt < 8; nt++) {
            float p0 = __expf(sc[nt][0] - mn1);
            float p1 = __expf(sc[nt][1] - mn1);
            float p2 = __expf(sc[nt][2] - mn2);
            float p3 = __expf(sc[nt][3] - mn2);
            rs1 += p0 + p1; rs2 += p2 + p3;
            int sl = 8*nt + 2*tig;
            Ps[(wr+gid  )*68 + sl    ] = to_tf32(p0);
            Ps[(wr+gid  )*68 + sl + 1] = to_tf32(p1);
            Ps[(wr+gid+8)*68 + sl    ] = to_tf32(p2);
            Ps[(wr+gid+8)*68 + sl + 1] = to_tf32(p3);
        }
        rs1 += __shfl_xor_sync(0xffffffffu, rs1, 1);
        rs1 += __shfl_xor_sync(0xffffffffu, rs1, 2);
        rs2 += __shfl_xor_sync(0xffffffffu, rs2, 1);
        rs2 += __shfl_xor_sync(0xffffffffu, rs2, 2);

        float f1 = __expf(m1 - mn1), f2 = __expf(m2 - mn2);
        l1 = l1 * f1 + rs1; l2 = l2 * f2 + rs2;
        m1 = mn1; m2 = mn2;
        #pragma unroll
        for (int nt = 0; nt < 8; nt++) {
            o[nt][0] *= f1; o[nt][1] *= f1;
            o[nt][2] *= f2; o[nt][3] *= f2;
        }
        __syncwarp();

        // O += P V : m16 (q) x n64 (ch) x k64 (s) — P rows owned by this warp
        #pragma unroll
        for (int kk = 0; kk < 64; kk += 8) {
            uint32_t a[4];
            a[0] = fu(Ps[(wr+gid  )*68 + kk+tig  ]);
            a[1] = fu(Ps[(wr+gid+8)*68 + kk+tig  ]);
            a[2] = fu(Ps[(wr+gid  )*68 + kk+4+tig]);
            a[3] = fu(Ps[(wr+gid+8)*68 + kk+4+tig]);
            #pragma unroll
            for (int nt = 0; nt < 8; nt++) {
                uint32_t bf[2];
                bf[0] = fu(Vs[(kk+tig  )*68 + 8*nt+gid]);
                bf[1] = fu(Vs[(kk+4+tig)*68 + 8*nt+gid]);
                mma_tf32(o[nt], a, bf);
            }
        }
    }

    float i1 = 1.f / l1, i2 = 1.f / l2;
    #pragma unroll
    for (int nt = 0; nt < 8; nt++) {
        o[nt][0] *= i1; o[nt][1] *= i1;
        o[nt][2] *= i2; o[nt][3] *= i2;
    }

    // Stage O through smem (reuse Qs area) as [ch][t] for coalesced writes
    __syncthreads();
    float* Os = sm;  // [64][132]
    #pragma unroll
    for (int nt = 0; nt < 8; nt++) {
        int ch = 8*nt + 2*tig;
        Os[(ch  )*132 + wr+gid  ] = o[nt][0];
        Os[(ch+1)*132 + wr+gid  ] = o[nt][1];
        Os[(ch  )*132 + wr+gid+8] = o[nt][2];
        Os[(ch+1)*132 + wr+gid+8] = o[nt][3];
    }
    __syncthreads();
    float* outb = g_attn + ((size_t)b * C_ + h * 64) * T_ + q0;
    for (int i = tid; i < 2048; i += 256) {
        int row = i >> 5, col = (i & 31) * 4;
        *(float4*)(outb + (size_t)row * T_ + col) = *(float4*)&Os[row*132 + col];
    }
}

// ---------------------------------------------------------------------------
extern "C" void kernel_launch(void* const* d_in, const int* in_sizes, int n_in,
                              void* d_out, int out_size)
{
    const float* x   = (const float*)d_in[0];
    const float* c   = (const float*)d_in[1];
    const float* wq  = (const float*)d_in[2];
    const float* bq  = (const float*)d_in[3];
    const float* wk  = (const float*)d_in[4];
    const float* bk  = (const float*)d_in[5];
    const float* wv  = (const float*)d_in[6];
    const float* bv  = (const float*)d_in[7];
    const float* wo  = (const float*)d_in[8];
    const float* bo  = (const float*)d_in[9];
    const float* erk = (const float*)d_in[10];
    // d_in[11] = emb_rel_v: unused by the reference output

    dim3 ggrid(T_/128, C_/128, B_);
    dim3 blk(256);
    const float scale = 0.125f;  // 1/sqrt(64), baked into q

    gemm_mma<<<ggrid, blk>>>(wq, x, bq, nullptr, scale, 0);
    gemm_mma<<<ggrid, blk>>>(wk, c, bk, nullptr, 1.0f, 1);
    gemm_mma<<<ggrid, blk>>>(wv, c, bv, nullptr, 1.0f, 2);

    cudaFuncSetAttribute(flash_mma,
                         cudaFuncAttributeMaxDynamicSharedMemorySize,
                         FL_SMEM_BYTES);
    dim3 fgrid(T_/128, H_, B_);
    flash_mma<<<fgrid, blk, FL_SMEM_BYTES>>>(erk);

    gemm_mma<<<ggrid, blk>>>(wo, nullptr, bo, (float*)d_out, 1.0f, 3);
}

// round 3
// speedup vs baseline: 2.0627x; 1.0000x over previous
#include <cuda_runtime.h>
#include <cuda_bf16.h>
#include <cstdint>

#define B_  8
#define C_  1024
#define T_  1024
#define H_  16
#define KC_ 64

// Scratch (static device globals — no allocations)
__device__ float g_q[(size_t)B_*H_*T_*KC_];
__device__ float g_k[(size_t)B_*H_*T_*KC_];
__device__ float g_v[(size_t)B_*H_*T_*KC_];
__device__ float g_attn[(size_t)B_*C_*T_];

__device__ __forceinline__ float to_tf32(float x) {
    float r; asm("cvt.rna.tf32.f32 %0, %1;" : "=f"(r) : "f"(x)); return r;
}
__device__ __forceinline__ uint32_t fu(float x) { return __float_as_uint(x); }

__device__ __forceinline__ void mma_tf32(float* c, const uint32_t* a, const uint32_t* b) {
    asm volatile(
        "mma.sync.aligned.m16n8k8.row.col.f32.tf32.tf32.f32 "
        "{%0,%1,%2,%3}, {%4,%5,%6,%7}, {%8,%9}, {%0,%1,%2,%3};"
        : "+f"(c[0]), "+f"(c[1]), "+f"(c[2]), "+f"(c[3])
        : "r"(a[0]), "r"(a[1]), "r"(a[2]), "r"(a[3]), "r"(b[0]), "r"(b[1]));
}

// ---------------------------------------------------------------------------
// Projection GEMM via mma.tf32:  out[b,o,t] = sum_c W[o,c] * X[b,c,t] + bias[o]
// Block tile 128x128, K-stage 32. 8 warps (4m x 2n), warp tile 32x64.
// mode 0/1/2: write g_q/g_k/g_v as [b,h,t,ch] (*scale); mode 3: X=g_attn -> dout
// ---------------------------------------------------------------------------
__global__ __launch_bounds__(256) void gemm_mma(
    const float* __restrict__ W, const float* __restrict__ Xin,
    const float* __restrict__ bias, float* __restrict__ dout,
    float scale, int mode)
{
    const float* X = (mode == 3) ? (const float*)g_attn : Xin;
    const int b  = blockIdx.z;
    const int o0 = blockIdx.y * 128;
    const int t0 = blockIdx.x * 128;
    const int tid = threadIdx.x, lane = tid & 31, w = tid >> 5;
    const int wm = (w >> 1) * 32, wn = (w & 1) * 64;
    const int gid = lane >> 2, tig = lane & 3;

    __shared__ float As[32][132];   // [k][m]  (W tile, transposed)
    __shared__ float Bs[32][132];   // [k][n]  (X tile)

    float acc[2][8][4];
    #pragma unroll
    for (int mt = 0; mt < 2; mt++)
        #pragma unroll
        for (int nt = 0; nt < 8; nt++)
            #pragma unroll
            for (int r = 0; r < 4; r++) acc[mt][nt][r] = 0.f;

    const float* Xb = X + (size_t)b * C_ * T_;
    const int am = tid >> 1, ak = (tid & 1) * 16;
    const int bk = tid >> 3, bn = (tid & 7) * 16;
    const float* Wp = W  + (size_t)(o0 + am) * C_ + ak;
    const float* Xp = Xb + (size_t)bk * T_ + t0 + bn;

    for (int k0 = 0; k0 < C_; k0 += 32) {
        #pragma unroll
        for (int i = 0; i < 4; i++) {
            float4 wv = *(const float4*)(Wp + k0 + 4*i);
            As[ak+4*i+0][am] = to_tf32(wv.x);
            As[ak+4*i+1][am] = to_tf32(wv.y);
            As[ak+4*i+2][am] = to_tf32(wv.z);
            As[ak+4*i+3][am] = to_tf32(wv.w);
            float4 xv = *(const float4*)(Xp + (size_t)k0 * T_ + 4*i);
            xv.x = to_tf32(xv.x); xv.y = to_tf32(xv.y);
            xv.z = to_tf32(xv.z); xv.w = to_tf32(xv.w);
            *(float4*)&Bs[bk][bn + 4*i] = xv;
        }
        __syncthreads();
        #pragma unroll
        for (int kk = 0; kk < 32; kk += 8) {
            uint32_t a[2][4], bf[8][2];
            #pragma unroll
            for (int mt = 0; mt < 2; mt++) {
                int m = wm + 16*mt + gid;
                a[mt][0] = fu(As[kk+tig  ][m  ]);
                a[mt][1] = fu(As[kk+tig  ][m+8]);
                a[mt][2] = fu(As[kk+4+tig][m  ]);
                a[mt][3] = fu(As[kk+4+tig][m+8]);
            }
            #pragma unroll
            for (int nt = 0; nt < 8; nt++) {
                int n = wn + 8*nt + gid;
                bf[nt][0] = fu(Bs[kk+tig  ][n]);
                bf[nt][1] = fu(Bs[kk+4+tig][n]);
            }
            #pragma unroll
            for (int mt = 0; mt < 2; mt++)
                #pragma unroll
                for (int nt = 0; nt < 8; nt++)
                    mma_tf32(acc[mt][nt], a[mt], bf[nt]);
        }
        __syncthreads();
    }

    // Epilogue. C frag: c0=(r, 2*tig), c1=(r, 2*tig+1), c2=(r+8, ..), c3.
    if (mode == 3) {
        #pragma unroll
        for (int mt = 0; mt < 2; mt++) {
            int oa = o0 + wm + 16*mt + gid;
            int ob = oa + 8;
            float ba = bias[oa], bb = bias[ob];
            #pragma unroll
            for (int nt = 0; nt < 8; nt++) {
                int t = t0 + wn + 8*nt + 2*tig;
                float2 v01 = make_float2(acc[mt][nt][0] + ba, acc[mt][nt][1] + ba);
                float2 v23 = make_float2(acc[mt][nt][2] + bb, acc[mt][nt][3] + bb);
                *(float2*)(dout + ((size_t)b * C_ + oa) * T_ + t) = v01;
                *(float2*)(dout + ((size_t)b * C_ + ob) * T_ + t) = v23;
            }
        }
    } else {
        float* outp = (mode == 0) ? g_q : (mode == 1) ? g_k : g_v;
        #pragma unroll
        for (int mt = 0; mt < 2; mt++) {
            int oa = o0 + wm + 16*mt + gid;
            int ob = oa + 8;
            float ba = bias[oa], bb = bias[ob];
            int ha = oa >> 6, ca = oa & 63;
            int hb = ob >> 6, cb = ob & 63;
            float* pa = outp + ((size_t)b * H_ + ha) * T_ * KC_;
            float* pb = outp + ((size_t)b * H_ + hb) * T_ * KC_;
            #pragma unroll
            for (int nt = 0; nt < 8; nt++) {
                int t = t0 + wn + 8*nt + 2*tig;
                pa[(size_t)t     * KC_ + ca] = (acc[mt][nt][0] + ba) * scale;
                pa[(size_t)(t+1) * KC_ + ca] = (acc[mt][nt][1] + ba) * scale;
                pb[(size_t)t     * KC_ + cb] = (acc[mt][nt][2] + bb) * scale;
                pb[(size_t)(t+1) * KC_ + cb] = (acc[mt][nt][3] + bb) * scale;
            }
        }
    }
}

// ---------------------------------------------------------------------------
// Flash attention, mma.tf32. Q tile = 128 rows, 8 warps (one m16 slice each).
// bias[t,s] = Rb[t][clip(s-t,-4,4)+4],  Rb[t][j] = q_t . emb_rel_k[j]
// ---------------------------------------------------------------------------
#define FL_SMEM_FLOATS (128*68 + 64*68 + 64*68 + 128*68 + 576 + 1536)
#define FL_SMEM_BYTES  (FL_SMEM_FLOATS * 4)

__global__ __launch_bounds__(256) void flash_mma(const float* __restrict__ emb)
{
    extern __shared__ float sm[];
    float* Qs = sm;               // [128][68]  (tf32)
    float* Ks = Qs + 128*68;      // [64][68]
    float* Vs = Ks + 64*68;       // [64][68]
    float* Ps = Vs + 64*68;       // [128][68]  (tf32 probabilities)
    float* Eb = Ps + 128*68;      // [9][64]
    float* Rb = Eb + 576;         // [128][12]

    const int b = blockIdx.z, h = blockIdx.y, q0 = blockIdx.x * 128;
    const int tid = threadIdx.x, lane = tid & 31, w = tid >> 5;
    const int gid = lane >> 2, tig = lane & 3;
    const int wr = 16 * w;

    const size_t bh = ((size_t)b * H_ + h) * T_ * KC_;
    const float* Qg = g_q + bh;
    const float* Kg = g_k + bh;
    const float* Vg = g_v + bh;

    // Load Q tile (tf32-rounded)
    {
        int r = tid >> 1, c0 = (tid & 1) * 32;
        #pragma unroll
        for (int i = 0; i < 8; i++) {
            float4 v = *(const float4*)(Qg + (size_t)(q0 + r) * KC_ + c0 + 4*i);
            v.x = to_tf32(v.x); v.y = to_tf32(v.y);
            v.z = to_tf32(v.z); v.w = to_tf32(v.w);
            *(float4*)&Qs[r*68 + c0 + 4*i] = v;
        }
    }
    if (tid < 144) ((float4*)Eb)[tid] = ((const float4*)emb)[tid];  // 9*64 floats
    __syncthreads();

    // Rb[r][j] = sum_ch Qs[r][ch] * Eb[j][ch]   (q already scaled)
    {
        int r = tid & 127;
        for (int j = tid >> 7; j < 9; j += 2) {
            float s = 0.f;
            #pragma unroll
            for (int ch = 0; ch < 64; ch++)
                s = fmaf(Qs[r*68 + ch], Eb[j*64 + ch], s);
            Rb[r*12 + j] = s;
        }
    }
    __syncthreads();

    float m1 = -1e30f, m2 = -1e30f, l1 = 0.f, l2 = 0.f;
    float o[8][4];
    #pragma unroll
    for (int nt = 0; nt < 8; nt++)
        #pragma unroll
        for (int r = 0; r < 4; r++) o[nt][r] = 0.f;

    for (int k0 = 0; k0 < T_; k0 += 64) {
        __syncthreads();  // previous iteration's readers of Ks/Vs done
        {
            int r = tid >> 2, c0 = (tid & 3) * 16;
            #pragma unroll
            for (int i = 0; i < 4; i++) {
                float4 kv = *(const float4*)(Kg + (size_t)(k0 + r) * KC_ + c0 + 4*i);
                kv.x = to_tf32(kv.x); kv.y = to_tf32(kv.y);
                kv.z = to_tf32(kv.z); kv.w = to_tf32(kv.w);
                *(float4*)&Ks[r*68 + c0 + 4*i] = kv;
                float4 vv = *(const float4*)(Vg + (size_t)(k0 + r) * KC_ + c0 + 4*i);
                vv.x = to_tf32(vv.x); vv.y = to_tf32(vv.y);
                vv.z = to_tf32(vv.z); vv.w = to_tf32(vv.w);
                *(float4*)&Vs[r*68 + c0 + 4*i] = vv;
            }
        }
        __syncthreads();

        // S = Q K^T : m16 (q rows wr..wr+15) x n64 (s) x k64 (ch)
        float sc[8][4];
        #pragma unroll
        for (int nt = 0; nt < 8; nt++)
            #pragma unroll
            for (int r = 0; r < 4; r++) sc[nt][r] = 0.f;

        #pragma unroll
        for (int kk = 0; kk < 64; kk += 8) {
            uint32_t a[4];
            a[0] = fu(Qs[(wr+gid  )*68 + kk+tig  ]);
            a[1] = fu(Qs[(wr+gid+8)*68 + kk+tig  ]);
            a[2] = fu(Qs[(wr+gid  )*68 + kk+4+tig]);
            a[3] = fu(Qs[(wr+gid+8)*68 + kk+4+tig]);
            #pragma unroll
            for (int nt = 0; nt < 8; nt++) {
                uint32_t bf[2];
                bf[0] = fu(Ks[(8*nt+gid)*68 + kk+tig  ]);
                bf[1] = fu(Ks[(8*nt+gid)*68 + kk+4+tig]);
                mma_tf32(sc[nt], a, bf);
            }
        }

        // relative-position bias
        const int t1 = q0 + wr + gid, t2 = t1 + 8;
        #pragma unroll
        for (int nt = 0; nt < 8; nt++) {
            int s0 = k0 + 8*nt + 2*tig;
            int d0 = min(max(s0   - t1, -4), 4) + 4;
            int d1 = min(max(s0+1 - t1, -4), 4) + 4;
            int d2 = min(max(s0   - t2, -4), 4) + 4;
            int d3 = min(max(s0+1 - t2, -4), 4) + 4;
            sc[nt][0] += Rb[(wr+gid  )*12 + d0];
            sc[nt][1] += Rb[(wr+gid  )*12 + d1];
            sc[nt][2] += Rb[(wr+gid+8)*12 + d2];
            sc[nt][3] += Rb[(wr+gid+8)*12 + d3];
        }

        // online softmax for the two rows this thread covers
        float mx1 = -1e30f, mx2 = -1e30f;
        #pragma unroll
        for (int nt = 0; nt < 8; nt++) {
            mx1 = fmaxf(mx1, fmaxf(sc[nt][0], sc[nt][1]));
            mx2 = fmaxf(mx2, fmaxf(sc[nt][2], sc[nt][3]));
        }
        mx1 = fmaxf(mx1, __shfl_xor_sync(0xffffffffu, mx1, 1));
        mx1 = fmaxf(mx1, __shfl_xor_sync(0xffffffffu, mx1, 2));
        mx2 = fmaxf(mx2, __shfl_xor_sync(0xffffffffu, mx2, 1));
        mx2 = fmaxf(mx2, __shfl_xor_sync(0xffffffffu, mx2, 2));
        float mn1 = fmaxf(m1, mx1), mn2 = fmaxf(m2, mx2);

        float rs1 = 0.f, rs2 = 0.f;
        #pragma unroll
        for (int nt = 0; nt < 8; nt++) {
            float p0 = __expf(sc[nt][0] - mn1);
            float p1 = __expf(sc[nt][1] - mn1);
            float p2 = __expf(sc[nt][2] - mn2);
            float p3 = __expf(sc[nt][3] - mn2);
            rs1 += p0 + p1; rs2 += p2 + p3;
            int sl = 8*nt + 2*tig;
            Ps[(wr+gid  )*68 + sl    ] = to_tf32(p0);
            Ps[(wr+gid  )*68 + sl + 1] = to_tf32(p1);
            Ps[(wr+gid+8)*68 + sl    ] = to_tf32(p2);
            Ps[(wr+gid+8)*68 + sl + 1] = to_tf32(p3);
        }
        rs1 += __shfl_xor_sync(0xffffffffu, rs1, 1);
        rs1 += __shfl_xor_sync(0xffffffffu, rs1, 2);
        rs2 += __shfl_xor_sync(0xffffffffu, rs2, 1);
        rs2 += __shfl_xor_sync(0xffffffffu, rs2, 2);

        float f1 = __expf(m1 - mn1), f2 = __expf(m2 - mn2);
        l1 = l1 * f1 + rs1; l2 = l2 * f2 + rs2;
        m1 = mn1; m2 = mn2;
        #pragma unroll
        for (int nt = 0; nt < 8; nt++) {
            o[nt][0] *= f1; o[nt][1] *= f1;
            o[nt][2] *= f2; o[nt][3] *= f2;
        }
        __syncwarp();

        // O += P V : m16 (q) x n64 (ch) x k64 (s) — P rows owned by this warp
        #pragma unroll
        for (int kk = 0; kk < 64; kk += 8) {
            uint32_t a[4];
            a[0] = fu(Ps[(wr+gid  )*68 + kk+tig  ]);
            a[1] = fu(Ps[(wr+gid+8)*68 + kk+tig  ]);
            a[2] = fu(Ps[(wr+gid  )*68 + kk+4+tig]);
            a[3] = fu(Ps[(wr+gid+8)*68 + kk+4+tig]);
            #pragma unroll
            for (int nt = 0; nt < 8; nt++) {
                uint32_t bf[2];
                bf[0] = fu(Vs[(kk+tig  )*68 + 8*nt+gid]);
                bf[1] = fu(Vs[(kk+4+tig)*68 + 8*nt+gid]);
                mma_tf32(o[nt], a, bf);
            }
        }
    }

    float i1 = 1.f / l1, i2 = 1.f / l2;
    #pragma unroll
    for (int nt = 0; nt < 8; nt++) {
        o[nt][0] *= i1; o[nt][1] *= i1;
        o[nt][2] *= i2; o[nt][3] *= i2;
    }

    // Stage O through smem (reuse Qs area) as [ch][t] for coalesced writes
    __syncthreads();
    float* Os = sm;  // [64][132]
    #pragma unroll
    for (int nt = 0; nt < 8; nt++) {
        int ch = 8*nt + 2*tig;
        Os[(ch  )*132 + wr+gid  ] = o[nt][0];
        Os[(ch+1)*132 + wr+gid  ] = o[nt][1];
        Os[(ch  )*132 + wr+gid+8] = o[nt][2];
        Os[(ch+1)*132 + wr+gid+8] = o[nt][3];
    }
    __syncthreads();
    float* outb = g_attn + ((size_t)b * C_ + h * 64) * T_ + q0;
    for (int i = tid; i < 2048; i += 256) {
        int row = i >> 5, col = (i & 31) * 4;
        *(float4*)(outb + (size_t)row * T_ + col) = *(float4*)&Os[row*132 + col];
    }
}

// ---------------------------------------------------------------------------
extern "C" void kernel_launch(void* const* d_in, const int* in_sizes, int n_in,
                              void* d_out, int out_size)
{
    const float* x   = (const float*)d_in[0];
    const float* c   = (const float*)d_in[1];
    const float* wq  = (const float*)d_in[2];
    const float* bq  = (const float*)d_in[3];
    const float* wk  = (const float*)d_in[4];
    const float* bk  = (const float*)d_in[5];
    const float* wv  = (const float*)d_in[6];
    const float* bv  = (const float*)d_in[7];
    const float* wo  = (const float*)d_in[8];
    const float* bo  = (const float*)d_in[9];
    const float* erk = (const float*)d_in[10];
    // d_in[11] = emb_rel_v: unused by the reference output

    dim3 ggrid(T_/128, C_/128, B_);
    dim3 blk(256);
    const float scale = 0.125f;  // 1/sqrt(64), baked into q

    gemm_mma<<<ggrid, blk>>>(wq, x, bq, nullptr, scale, 0);
    gemm_mma<<<ggrid, blk>>>(wk, c, bk, nullptr, 1.0f, 1);
    gemm_mma<<<ggrid, blk>>>(wv, c, bv, nullptr, 1.0f, 2);

    cudaFuncSetAttribute(flash_mma,
                         cudaFuncAttributeMaxDynamicSharedMemorySize,
                         FL_SMEM_BYTES);
    dim3 fgrid(T_/128, H_, B_);
    flash_mma<<<fgrid, blk, FL_SMEM_BYTES>>>(erk);

    gemm_mma<<<ggrid, blk>>>(wo, nullptr, bo, (float*)d_out, 1.0f, 3);
}